// round 15
// baseline (speedup 1.0000x reference)
#include <cuda_runtime.h>
#include <math.h>

#define N 512
#define D 128
#define DEPTH 4
#define TT 32
#define SC 16            // real s-chunk size
#define WC 32            // W-chunk size
#define NREAL 272        // sum over a=0..15 of (2a+2)
#define NBLK 336         // 272 real + 64 W blocks
#define NSLICE 36        // 32 real + 4 W slices
#define STR 132
#define PSTR 20
#define CSTR 20

// ---------------- scratch ----------------
__device__ float g_q[N*D];
__device__ float g_X[N*D];
__device__ float g_v[N*D];
__device__ float g_Z[3*N*D];
__device__ float g_lr[N], g_am[N], g_dk[N];
__device__ float g_A[DEPTH*N*D];
__device__ float g_G[DEPTH*N*D];
__device__ float g_WT[DEPTH*D*D];
__device__ float g_WqT[D*D];
__device__ float g_WkT[D*D];
__device__ float g_WvT[D*D];
__device__ float g_Chat[N*N];
__device__ float g_Yp[NSLICE*N*D];

__device__ __forceinline__ float siluf(float z){
    float s = 1.f/(1.f+__expf(-z));
    return z*s;
}
__device__ __forceinline__ float dsiluf(float z){
    float s = 1.f/(1.f+__expf(-z));
    return s*(1.f + z*(1.f-s));
}

// ---------------- transposes ----------------
__global__ void tr_kernel(const float* __restrict__ Wmem,
                          const float* __restrict__ Wq,
                          const float* __restrict__ Wkv){
    int l = blockIdx.x;
    for (int e = threadIdx.x; e < D*D; e += blockDim.x){
        int j = e >> 7, i = e & 127;
        if (l < 4)       g_WT[l*D*D + e] = Wmem[l*D*D + i*D + j];
        else if (l == 4) g_WqT[e] = Wq[i*D + j];
        else if (l == 5) g_WkT[e] = Wkv[i*2*D + j];
        else             g_WvT[e] = Wkv[i*2*D + D + j];
    }
}

// ---------------- per-token scalars: warp per token ----------------
__global__ __launch_bounds__(128) void scalars_kernel(const float* __restrict__ seq,
                                                      const float* __restrict__ Wstep,
                                                      const float* __restrict__ Wmom,
                                                      const float* __restrict__ Wdecay){
    int t = blockIdx.x*4 + (threadIdx.x >> 5);
    int lane = threadIdx.x & 31;
    float4 x = *reinterpret_cast<const float4*>(&seq[t*D + lane*4]);
    float4 a = *reinterpret_cast<const float4*>(&Wstep[lane*4]);
    float4 b = *reinterpret_cast<const float4*>(&Wmom[lane*4]);
    float4 c = *reinterpret_cast<const float4*>(&Wdecay[lane*4]);
    float p0 = x.x*a.x + x.y*a.y + x.z*a.z + x.w*a.w;
    float p1 = x.x*b.x + x.y*b.y + x.z*b.z + x.w*b.w;
    float p2 = x.x*c.x + x.y*c.y + x.z*c.z + x.w*c.w;
    #pragma unroll
    for (int o = 16; o > 0; o >>= 1){
        p0 += __shfl_xor_sync(0xffffffffu, p0, o);
        p1 += __shfl_xor_sync(0xffffffffu, p1, o);
        p2 += __shfl_xor_sync(0xffffffffu, p2, o);
    }
    if (lane == 0){
        g_lr[t] = p0;
        g_am[t] = p1;
        g_dk[t] = 1.f - 1.f/(1.f+__expf(-p2));
    }
}

// ---------------- generic GEMM stage: out[t][j] = src[t,:] . wt[j,:] ----------------
// grid.x = 512 (64 t-tiles x 8 j-chunks), 128 thr. L1 flushed per launch => plain loads coherent.
// mode 0: dst=c | mode 1: dst=c, dst2=silu(c) | mode 2: dst=(c-aux)*2/D | mode 3: dst=c*dsilu(aux)
__global__ __launch_bounds__(128) void stage_kernel(const float* __restrict__ src,
                                                    const float* __restrict__ wt,
                                                    float* __restrict__ dst,
                                                    float* __restrict__ dst2,
                                                    const float* __restrict__ aux,
                                                    int mode){
    __shared__ float Xs[8*STR];
    __shared__ float Ws[16*STR];
    int bx = blockIdx.x;
    int t0 = (bx >> 3)*8, j0 = (bx & 7)*16;
    int tid = threadIdx.x;

    for (int e = tid; e < 8*32; e += 128){
        int t = e >> 5, k4 = (e & 31)*4;
        *reinterpret_cast<float4*>(&Xs[t*STR + k4]) =
            *reinterpret_cast<const float4*>(&src[(t0+t)*D + k4]);
    }
    for (int e = tid; e < 16*32; e += 128){
        int r = e >> 5, k4 = (e & 31)*4;
        *reinterpret_cast<float4*>(&Ws[r*STR + k4]) =
            *reinterpret_cast<const float4*>(&wt[(j0+r)*D + k4]);
    }
    __syncthreads();

    int tx = tid & 15, ty = tid >> 4;
    const float* wr = Ws + tx*STR;
    const float* xr = Xs + ty*STR;
    float c = 0.f;
    #pragma unroll 8
    for (int k = 0; k < D; k += 4){
        float4 w = *reinterpret_cast<const float4*>(&wr[k]);
        float4 x = *reinterpret_cast<const float4*>(&xr[k]);
        c += x.x*w.x + x.y*w.y + x.z*w.z + x.w*w.w;
    }
    int idx = (t0 + ty)*D + (j0 + tx);
    if      (mode == 0) dst[idx] = c;
    else if (mode == 1){ dst[idx] = c; dst2[idx] = siluf(c); }
    else if (mode == 2) dst[idx] = (c - aux[idx])*(2.f/128.f);
    else                dst[idx] = c*dsiluf(aux[idx]);
}

// ---------------- qkv: 3 GEMMs in one launch via grid.y ----------------
__global__ __launch_bounds__(128) void qkv_kernel(const float* __restrict__ seq){
    __shared__ float Xs[8*STR];
    __shared__ float Ws[16*STR];
    int bx = blockIdx.x, by = blockIdx.y;
    const float* wt = (by == 0) ? g_WqT : (by == 1) ? g_WkT : g_WvT;
    float* dst      = (by == 0) ? g_q   : (by == 1) ? g_A   : g_v;
    int t0 = (bx >> 3)*8, j0 = (bx & 7)*16;
    int tid = threadIdx.x;

    for (int e = tid; e < 8*32; e += 128){
        int t = e >> 5, k4 = (e & 31)*4;
        *reinterpret_cast<float4*>(&Xs[t*STR + k4]) =
            *reinterpret_cast<const float4*>(&seq[(t0+t)*D + k4]);
    }
    for (int e = tid; e < 16*32; e += 128){
        int r = e >> 5, k4 = (e & 31)*4;
        *reinterpret_cast<float4*>(&Ws[r*STR + k4]) =
            *reinterpret_cast<const float4*>(&wt[(j0+r)*D + k4]);
    }
    __syncthreads();

    int tx = tid & 15, ty = tid >> 4;
    const float* wr = Ws + tx*STR;
    const float* xr = Xs + ty*STR;
    float c = 0.f;
    #pragma unroll 8
    for (int k = 0; k < D; k += 4){
        float4 w = *reinterpret_cast<const float4*>(&wr[k]);
        float4 x = *reinterpret_cast<const float4*>(&xr[k]);
        c += x.x*w.x + x.y*w.y + x.z*w.z + x.w*w.w;
    }
    dst[(t0 + ty)*D + (j0 + tx)] = c;
}

// ---------------- scan-coefficient matrix (parallel over s) ----------------
__global__ void chat_kernel(){
    __shared__ float sam[N], sdk[N];
    int s = blockIdx.x*128 + threadIdx.x;
    for (int i = threadIdx.x; i < N; i += 128){ sam[i] = g_am[i]; sdk[i] = g_dk[i]; }
    __syncthreads();
    float m = 0.f, c = 0.f;
    float nl = -g_lr[s];
    for (int t = 0; t < N; t++){
        float out;
        if (t < s) out = 0.f;
        else if (t == s){ m = 1.f; c = 1.f; out = nl; }
        else {
            m *= sam[t];
            c = sdk[t]*c + m;
            out = nl*c;
        }
        g_Chat[t*N + s] = out;
    }
}

// ---------------- fused attention layer (measured-best config) ----------------
__global__ __launch_bounds__(256) void layer_kernel(const float* __restrict__ Wmem,
                                                    int layer, int first){
    extern __shared__ float sm[];
    float* Xs = sm;                 // [TT][STR]
    float* As = Xs + TT*STR;        // [SC][STR]
    float* Gs = As + SC*STR;        // [WC][STR]
    float* Cs = Gs + WC*STR;        // [TT][CSTR]
    float* Ps = Cs + TT*CSTR;       // [TT][PSTR]

    int id = blockIdx.x;
    int a, b; bool isW;
    if (id < NREAL){
        int r = id; a = 0;
        while (r >= 2*a + 2){ r -= 2*a + 2; a++; }
        b = r; isW = false;
    } else {
        int q = id - NREAL; a = q >> 2; b = q & 3; isW = true;
    }
    int t0 = a*TT;
    int tid = threadIdx.x;

    const float* Xsrc = first ? g_q : g_X;
    for (int e = tid; e < TT*32; e += 256){
        int t = e >> 5, k4 = (e & 31)*4;
        *reinterpret_cast<float4*>(&Xs[t*STR + k4]) =
            *reinterpret_cast<const float4*>(&Xsrc[(t0+t)*D + k4]);
    }
    if (!isW){
        const float* Al = g_A + layer*N*D;
        const float* Gl = g_G + layer*N*D;
        int s0 = b*SC;
        for (int e = tid; e < SC*32; e += 256){
            int r = e >> 5, k4 = (e & 31)*4;
            *reinterpret_cast<float4*>(&As[r*STR + k4]) =
                *reinterpret_cast<const float4*>(&Al[(s0+r)*D + k4]);
        }
        for (int e = tid; e < SC*32; e += 256){
            int r = e >> 5, k4 = (e & 31)*4;
            *reinterpret_cast<float4*>(&Gs[r*STR + k4]) =
                *reinterpret_cast<const float4*>(&Gl[(s0+r)*D + k4]);
        }
        for (int e = tid; e < TT*4; e += 256){
            int t = e >> 2, s4 = (e & 3)*4;
            *reinterpret_cast<float4*>(&Cs[t*CSTR + s4]) =
                *reinterpret_cast<const float4*>(&g_Chat[(t0+t)*N + s0 + s4]);
        }
    } else {
        const float* Wl = Wmem + layer*D*D;
        int w0 = b*WC;
        for (int e = tid; e < WC*32; e += 256){
            int r = e >> 5, k4 = (e & 31)*4;
            *reinterpret_cast<float4*>(&Gs[r*STR + k4]) =
                *reinterpret_cast<const float4*>(&Wl[(w0+r)*D + k4]);
        }
    }
    __syncthreads();

    // ---- phase 1 (real): S = (X @ A^T) ⊙ Chat -> Ps ----
    if (!isW){
        int sx16 = tid & 15;
        int tg   = tid >> 4;
        float c0 = 0.f, c1 = 0.f;
        const float* ar  = As + sx16*STR;
        const float* x0r = Xs + (tg*2+0)*STR;
        const float* x1r = Xs + (tg*2+1)*STR;
        #pragma unroll 8
        for (int k = 0; k < D; k += 4){
            float4 av = *reinterpret_cast<const float4*>(&ar[k]);
            float4 x0 = *reinterpret_cast<const float4*>(&x0r[k]);
            float4 x1 = *reinterpret_cast<const float4*>(&x1r[k]);
            c0 += x0.x*av.x + x0.y*av.y + x0.z*av.z + x0.w*av.w;
            c1 += x1.x*av.x + x1.y*av.y + x1.z*av.z + x1.w*av.w;
        }
        Ps[(tg*2+0)*PSTR + sx16] = c0 * Cs[(tg*2+0)*CSTR + sx16];
        Ps[(tg*2+1)*PSTR + sx16] = c1 * Cs[(tg*2+1)*CSTR + sx16];
    }
    __syncthreads();

    // ---- phase 2: Y_slice = P @ G ----
    int tx = tid & 31, ty = tid >> 5;
    const float* Psrc = isW ? (Xs + b*WC) : Ps;
    int pst = isW ? STR : PSTR;
    int sc  = isW ? WC : SC;

    float y[4][4];
    #pragma unroll
    for (int i = 0; i < 4; i++)
        #pragma unroll
        for (int jj = 0; jj < 4; jj++) y[i][jj] = 0.f;

    #pragma unroll 4
    for (int s = 0; s < sc; s += 4){
        float4 g0 = *reinterpret_cast<const float4*>(&Gs[(s+0)*STR + tx*4]);
        float4 g1 = *reinterpret_cast<const float4*>(&Gs[(s+1)*STR + tx*4]);
        float4 g2 = *reinterpret_cast<const float4*>(&Gs[(s+2)*STR + tx*4]);
        float4 g3 = *reinterpret_cast<const float4*>(&Gs[(s+3)*STR + tx*4]);
        #pragma unroll
        for (int i = 0; i < 4; i++){
            float4 p = *reinterpret_cast<const float4*>(&Psrc[(ty*4+i)*pst + s]);
            y[i][0] += p.x*g0.x + p.y*g1.x + p.z*g2.x + p.w*g3.x;
            y[i][1] += p.x*g0.y + p.y*g1.y + p.z*g2.y + p.w*g3.y;
            y[i][2] += p.x*g0.z + p.y*g1.z + p.z*g2.z + p.w*g3.z;
            y[i][3] += p.x*g0.w + p.y*g1.w + p.z*g2.w + p.w*g3.w;
        }
    }
    int slice = isW ? (32 + b) : b;
    #pragma unroll
    for (int i = 0; i < 4; i++){
        float4 v; v.x=y[i][0]; v.y=y[i][1]; v.z=y[i][2]; v.w=y[i][3];
        *reinterpret_cast<float4*>(&g_Yp[((slice*N) + t0 + ty*4 + i)*D + tx*4]) = v;
    }
}

// ---------------- reduce: slice-parallel, one block per token ----------------
__global__ __launch_bounds__(128) void reduce_kernel(float* __restrict__ out, int last){
    int t = blockIdx.x;
    int tid = threadIdx.x;
    int tx = tid & 31, sg = tid >> 5;
    const float4* Yp = reinterpret_cast<const float4*>(g_Yp);
    int idx = t*32 + tx;

    float4 acc = Yp[(32 + sg)*(N*32) + idx];

    int nr = (t >> 4) + 1;
    #pragma unroll 4
    for (int c = sg; c < nr; c += 4){
        float4 p = Yp[c*(N*32) + idx];
        acc.x += p.x; acc.y += p.y; acc.z += p.z; acc.w += p.w;
    }

    __shared__ float4 sred[128];
    sred[tid] = acc;
    __syncthreads();
    if (sg == 0){
        float4 a = sred[tx], b = sred[32+tx], c2 = sred[64+tx], d = sred[96+tx];
        float ax = a.x+b.x+c2.x+d.x;
        float ay = a.y+b.y+c2.y+d.y;
        float az = a.z+b.z+c2.z+d.z;
        float aw = a.w+b.w+c2.w+d.w;
        float4 r;
        if (last){ r.x = ax; r.y = ay; r.z = az; r.w = aw; }
        else     { r.x = siluf(ax); r.y = siluf(ay); r.z = siluf(az); r.w = siluf(aw); }
        float4* dst = last ? reinterpret_cast<float4*>(out) : reinterpret_cast<float4*>(g_X);
        dst[idx] = r;
    }
}

// ---------------- launch ----------------
extern "C" void kernel_launch(void* const* d_in, const int* in_sizes, int n_in,
                              void* d_out, int out_size){
    const float* seq    = (const float*)d_in[0];
    const float* Wmem   = (const float*)d_in[1];
    const float* Wq     = (const float*)d_in[2];
    const float* Wkv    = (const float*)d_in[3];
    const float* Wmom   = (const float*)d_in[4];
    const float* Wstep  = (const float*)d_in[5];
    const float* Wdecay = (const float*)d_in[6];
    float* out = (float*)d_out;

    size_t smem = (size_t)(TT*STR + SC*STR + WC*STR + TT*CSTR + TT*PSTR)*sizeof(float); // 47360
    cudaFuncSetAttribute(layer_kernel, cudaFuncAttributeMaxDynamicSharedMemorySize, (int)smem);

    float* dZ  = nullptr; float* dA = nullptr; float* dG = nullptr;
    float* dv  = nullptr;
    cudaGetSymbolAddress((void**)&dZ, g_Z);
    cudaGetSymbolAddress((void**)&dA, g_A);
    cudaGetSymbolAddress((void**)&dG, g_G);
    cudaGetSymbolAddress((void**)&dv, g_v);
    float* dWT = nullptr;
    cudaGetSymbolAddress((void**)&dWT, g_WT);

    tr_kernel<<<7, 128>>>(Wmem, Wq, Wkv);
    scalars_kernel<<<N/4, 128>>>(seq, Wstep, Wmom, Wdecay);
    chat_kernel<<<4, 128>>>();

    dim3 qg(512, 3);
    qkv_kernel<<<qg, 128>>>(seq);
    // forward: z_l = A[l] @ W_l (via WT rows), A[l+1] = silu(z_l)
    stage_kernel<<<512, 128>>>(dA + 0*N*D, dWT + 0*D*D, dZ + 0*N*D, dA + 1*N*D, nullptr, 1);
    stage_kernel<<<512, 128>>>(dA + 1*N*D, dWT + 1*D*D, dZ + 1*N*D, dA + 2*N*D, nullptr, 1);
    stage_kernel<<<512, 128>>>(dA + 2*N*D, dWT + 2*D*D, dZ + 2*N*D, dA + 3*N*D, nullptr, 1);
    // z4 and g3
    stage_kernel<<<512, 128>>>(dA + 3*N*D, dWT + 3*D*D, dG + 3*N*D, nullptr, dv, 2);
    // backward: g_{l-1} = (g_l @ W_l^T) * dsilu(z_{l-1}); weight rows = Wmem rows
    stage_kernel<<<512, 128>>>(dG + 3*N*D, Wmem + 3*D*D, dG + 2*N*D, nullptr, dZ + 2*N*D, 3);
    stage_kernel<<<512, 128>>>(dG + 2*N*D, Wmem + 2*D*D, dG + 1*N*D, nullptr, dZ + 1*N*D, 3);
    stage_kernel<<<512, 128>>>(dG + 1*N*D, Wmem + 1*D*D, dG + 0*N*D, nullptr, dZ + 0*N*D, 3);

    layer_kernel<<<NBLK, 256, smem>>>(Wmem, 0, 1);
    reduce_kernel<<<N, 128>>>(out, 0);
    layer_kernel<<<NBLK, 256, smem>>>(Wmem, 1, 0);
    reduce_kernel<<<N, 128>>>(out, 0);
    layer_kernel<<<NBLK, 256, smem>>>(Wmem, 2, 0);
    reduce_kernel<<<N, 128>>>(out, 0);
    layer_kernel<<<NBLK, 256, smem>>>(Wmem, 3, 0);
    reduce_kernel<<<N, 128>>>(out, 1);
}

// round 16
// speedup vs baseline: 1.2284x; 1.2284x over previous
#include <cuda_runtime.h>
#include <math.h>

#define N 512
#define D 128
#define DEPTH 4
#define TT 32
#define SC 16            // real s-chunk size
#define WC 32            // W-chunk size
#define NREAL 272        // sum over a=0..15 of (2a+2)
#define NBLK 336         // 272 real + 64 W blocks
#define NSLICE 36        // 32 real + 4 W slices
#define STR 132
#define PSTR 20
#define CSTR 20

// ---------------- scratch ----------------
__device__ float g_q[N*D];
__device__ float g_X[N*D];
__device__ float g_lr[N], g_am[N], g_dk[N];
__device__ float g_A[DEPTH*N*D];
__device__ float g_G[DEPTH*N*D];
__device__ float g_WT[DEPTH*D*D];
__device__ float g_Chat[N*N];
__device__ float g_Yp[NSLICE*N*D];

__device__ __forceinline__ float siluf(float z){
    float s = 1.f/(1.f+__expf(-z));
    return z*s;
}
__device__ __forceinline__ float dsiluf(float z){
    float s = 1.f/(1.f+__expf(-z));
    return s*(1.f + z*(1.f-s));
}

// ---------------- transpose W_mem ----------------
__global__ void tr_kernel(const float* __restrict__ Wmem){
    int l = blockIdx.x;
    for (int e = threadIdx.x; e < D*D; e += blockDim.x){
        int j = e >> 7, i = e & 127;
        g_WT[l*D*D + e] = Wmem[l*D*D + i*D + j];
    }
}

// ---------------- 64 column-strided weight loads into registers ----------------
__device__ __forceinline__ void ldw64(const float* __restrict__ p, float w[64]){
    #pragma unroll
    for (int u = 0; u < 64; u++) w[u] = p[u*D];
}

// ---------------- 2-token x 64-i FMA with preloaded weights ----------------
__device__ __forceinline__ void fmaw(const float sxa[2][D], const float w[64],
                                     int base, float z[2]){
    #pragma unroll
    for (int m = 0; m < 2; m++){
        const float* xr = &sxa[m][base];
        float a0 = 0.f, a1 = 0.f;
        #pragma unroll
        for (int q = 0; q < 64; q += 8){
            float4 xa = *reinterpret_cast<const float4*>(&xr[q]);
            float4 xb = *reinterpret_cast<const float4*>(&xr[q+4]);
            a0 += xa.x*w[q]   + xa.y*w[q+1] + xa.z*w[q+2] + xa.w*w[q+3];
            a1 += xb.x*w[q+4] + xb.y*w[q+5] + xb.z*w[q+6] + xb.w*w[q+7];
        }
        z[m] = a0 + a1;
    }
}

// ---------------- per-token MLP fwd+bwd: 2 tokens/block, 256 thr, 256 blocks ----------------
__global__ __launch_bounds__(256) void token_kernel(const float* __restrict__ seq,
                             const float* __restrict__ Wmem,
                             const float* __restrict__ Wq,
                             const float* __restrict__ Wkv,
                             const float* __restrict__ Wmom,
                             const float* __restrict__ Wstep,
                             const float* __restrict__ Wdecay){
    int t0 = blockIdx.x*2;
    int tid = threadIdx.x;
    int j = tid & 127;
    int h = tid >> 7;
    const int base = h*64;
    const int coff = base*D + j;          // column offset for this thread's weight stream

    __shared__ float sx[2][D];
    __shared__ float sA[2][D];
    __shared__ float sB[2][D];
    __shared__ float sv[2][D];
    __shared__ float szp[3][2][2][D];
    __shared__ float red[6][4];

    for (int e = tid; e < 2*D; e += 256){
        int m = e >> 7, jj = e & 127;
        sx[m][jj] = seq[(t0+m)*D + jj];
    }
    __syncthreads();

    if (h == 0){
        float ws = Wstep[j], wm = Wmom[j], wd = Wdecay[j];
        #pragma unroll
        for (int m = 0; m < 2; m++){
            float xv = sx[m][j];
            float p0 = xv*ws, p1 = xv*wm, p2 = xv*wd;
            #pragma unroll
            for (int o = 16; o > 0; o >>= 1){
                p0 += __shfl_xor_sync(0xffffffffu, p0, o);
                p1 += __shfl_xor_sync(0xffffffffu, p1, o);
                p2 += __shfl_xor_sync(0xffffffffu, p2, o);
            }
            if ((j & 31) == 0){ red[m*3+0][j>>5]=p0; red[m*3+1][j>>5]=p1; red[m*3+2][j>>5]=p2; }
        }
    }

    // prefetch stage-0 weights (W0) while q/k/v runs
    float wA[64], wB[64];
    ldw64(Wmem + coff, wA);

    // q,k,v partials
    {
        float qa[2]={0,0}, ka[2]={0,0}, va[2]={0,0};
        const float* Wqh  = Wq  + base*D + j;
        const float* Wkh  = Wkv + base*2*D + j;
        const float* Wvh  = Wkv + base*2*D + D + j;
        for (int i = 0; i < 64; i += 8){
            float wq[8], wk[8], wv[8];
            #pragma unroll
            for (int u = 0; u < 8; u++){
                wq[u] = Wqh[(i+u)*D];
                wk[u] = Wkh[(i+u)*2*D];
                wv[u] = Wvh[(i+u)*2*D];
            }
            #pragma unroll
            for (int m = 0; m < 2; m++){
                const float* xr = &sx[m][base+i];
                float4 xa = *reinterpret_cast<const float4*>(&xr[0]);
                float4 xb = *reinterpret_cast<const float4*>(&xr[4]);
                qa[m] += xa.x*wq[0]+xa.y*wq[1]+xa.z*wq[2]+xa.w*wq[3]
                       + xb.x*wq[4]+xb.y*wq[5]+xb.z*wq[6]+xb.w*wq[7];
                ka[m] += xa.x*wk[0]+xa.y*wk[1]+xa.z*wk[2]+xa.w*wk[3]
                       + xb.x*wk[4]+xb.y*wk[5]+xb.z*wk[6]+xb.w*wk[7];
                va[m] += xa.x*wv[0]+xa.y*wv[1]+xa.z*wv[2]+xa.w*wv[3]
                       + xb.x*wv[4]+xb.y*wv[5]+xb.z*wv[6]+xb.w*wv[7];
            }
        }
        #pragma unroll
        for (int m = 0; m < 2; m++){
            szp[0][h][m][j] = qa[m];
            szp[1][h][m][j] = ka[m];
            szp[2][h][m][j] = va[m];
        }
    }
    __syncthreads();
    if (h == 0){
        if (j < 2){
            g_lr[t0+j] = red[j*3+0][0]+red[j*3+0][1]+red[j*3+0][2]+red[j*3+0][3];
            g_am[t0+j] = red[j*3+1][0]+red[j*3+1][1]+red[j*3+1][2]+red[j*3+1][3];
            float dz = red[j*3+2][0]+red[j*3+2][1]+red[j*3+2][2]+red[j*3+2][3];
            g_dk[t0+j] = 1.f - 1.f/(1.f+__expf(-dz));
        }
        #pragma unroll
        for (int m = 0; m < 2; m++){
            g_q[(t0+m)*D + j] = szp[0][0][m][j] + szp[0][1][m][j];
            float kk = szp[1][0][m][j] + szp[1][1][m][j];
            sA[m][j] = kk; g_A[0*N*D + (t0+m)*D + j] = kk;
            sv[m][j] = szp[2][0][m][j] + szp[2][1][m][j];
        }
    }
    __syncthreads();

    float z1[2], z2[2], z3[2], zp[2], z[2];

    // stage 0: z1 = k @ W0  (wA; prefetch W1 -> wB)
    ldw64(Wmem + 1*D*D + coff, wB);
    fmaw(sA, wA, base, zp);
    #pragma unroll
    for (int m = 0; m < 2; m++) szp[0][h][m][j] = zp[m];
    __syncthreads();
    #pragma unroll
    for (int m = 0; m < 2; m++){
        z[m] = szp[0][0][m][j] + szp[0][1][m][j]; z1[m] = z[m];
        if (h == 0){ float x1 = siluf(z[m]); sB[m][j] = x1; g_A[1*N*D + (t0+m)*D + j] = x1; }
    }
    __syncthreads();

    // stage 1: z2 = x1 @ W1  (wB; prefetch W2 -> wA)
    ldw64(Wmem + 2*D*D + coff, wA);
    fmaw(sB, wB, base, zp);
    #pragma unroll
    for (int m = 0; m < 2; m++) szp[0][h][m][j] = zp[m];
    __syncthreads();
    #pragma unroll
    for (int m = 0; m < 2; m++){
        z[m] = szp[0][0][m][j] + szp[0][1][m][j]; z2[m] = z[m];
        if (h == 0){ float x2 = siluf(z[m]); sA[m][j] = x2; g_A[2*N*D + (t0+m)*D + j] = x2; }
    }
    __syncthreads();

    // stage 2: z3 = x2 @ W2  (wA; prefetch W3 -> wB)
    ldw64(Wmem + 3*D*D + coff, wB);
    fmaw(sA, wA, base, zp);
    #pragma unroll
    for (int m = 0; m < 2; m++) szp[0][h][m][j] = zp[m];
    __syncthreads();
    #pragma unroll
    for (int m = 0; m < 2; m++){
        z[m] = szp[0][0][m][j] + szp[0][1][m][j]; z3[m] = z[m];
        if (h == 0){ float x3 = siluf(z[m]); sB[m][j] = x3; g_A[3*N*D + (t0+m)*D + j] = x3; }
    }
    __syncthreads();

    // stage 3: z4 = x3 @ W3 ; g3  (wB; prefetch WT3 -> wA)
    ldw64(g_WT + 3*D*D + coff, wA);
    fmaw(sB, wB, base, zp);
    #pragma unroll
    for (int m = 0; m < 2; m++) szp[0][h][m][j] = zp[m];
    __syncthreads();
    #pragma unroll
    for (int m = 0; m < 2; m++){
        z[m] = szp[0][0][m][j] + szp[0][1][m][j];
        if (h == 0){
            float gg = (z[m] - sv[m][j]) * (2.f/(float)D);
            sA[m][j] = gg; g_G[3*N*D + (t0+m)*D + j] = gg;
        }
    }
    __syncthreads();

    // stage 4: dx = g3 @ W3^T ; g2  (wA; prefetch WT2 -> wB)
    ldw64(g_WT + 2*D*D + coff, wB);
    fmaw(sA, wA, base, zp);
    #pragma unroll
    for (int m = 0; m < 2; m++) szp[0][h][m][j] = zp[m];
    __syncthreads();
    #pragma unroll
    for (int m = 0; m < 2; m++){
        z[m] = szp[0][0][m][j] + szp[0][1][m][j];
        if (h == 0){
            float gg = z[m]*dsiluf(z3[m]);
            sB[m][j] = gg; g_G[2*N*D + (t0+m)*D + j] = gg;
        }
    }
    __syncthreads();

    // stage 5: dx = g2 @ W2^T ; g1  (wB; prefetch WT1 -> wA)
    ldw64(g_WT + 1*D*D + coff, wA);
    fmaw(sB, wB, base, zp);
    #pragma unroll
    for (int m = 0; m < 2; m++) szp[0][h][m][j] = zp[m];
    __syncthreads();
    #pragma unroll
    for (int m = 0; m < 2; m++){
        z[m] = szp[0][0][m][j] + szp[0][1][m][j];
        if (h == 0){
            float gg = z[m]*dsiluf(z2[m]);
            sA[m][j] = gg; g_G[1*N*D + (t0+m)*D + j] = gg;
        }
    }
    __syncthreads();

    // stage 6: dx = g1 @ W1^T ; g0  (wA)
    fmaw(sA, wA, base, zp);
    #pragma unroll
    for (int m = 0; m < 2; m++) szp[0][h][m][j] = zp[m];
    __syncthreads();
    if (h == 0){
        #pragma unroll
        for (int m = 0; m < 2; m++){
            float zz = szp[0][0][m][j] + szp[0][1][m][j];
            g_G[0*N*D + (t0+m)*D + j] = zz*dsiluf(z1[m]);
        }
    }
}

// ---------------- scan-coefficient matrix (parallel over s) ----------------
__global__ void chat_kernel(){
    __shared__ float sam[N], sdk[N];
    int s = blockIdx.x*128 + threadIdx.x;
    for (int i = threadIdx.x; i < N; i += 128){ sam[i] = g_am[i]; sdk[i] = g_dk[i]; }
    __syncthreads();
    float m = 0.f, c = 0.f;
    float nl = -g_lr[s];
    for (int t = 0; t < N; t++){
        float out;
        if (t < s) out = 0.f;
        else if (t == s){ m = 1.f; c = 1.f; out = nl; }
        else {
            m *= sam[t];
            c = sdk[t]*c + m;
            out = nl*c;
        }
        g_Chat[t*N + s] = out;
    }
}

// ---------------- fused attention layer (measured-best config) ----------------
__global__ __launch_bounds__(256) void layer_kernel(const float* __restrict__ Wmem,
                                                    int layer, int first){
    extern __shared__ float sm[];
    float* Xs = sm;                 // [TT][STR]
    float* As = Xs + TT*STR;        // [SC][STR]
    float* Gs = As + SC*STR;        // [WC][STR]
    float* Cs = Gs + WC*STR;        // [TT][CSTR]
    float* Ps = Cs + TT*CSTR;       // [TT][PSTR]

    int id = blockIdx.x;
    int a, b; bool isW;
    if (id < NREAL){
        int r = id; a = 0;
        while (r >= 2*a + 2){ r -= 2*a + 2; a++; }
        b = r; isW = false;
    } else {
        int q = id - NREAL; a = q >> 2; b = q & 3; isW = true;
    }
    int t0 = a*TT;
    int tid = threadIdx.x;

    const float* Xsrc = first ? g_q : g_X;
    for (int e = tid; e < TT*32; e += 256){
        int t = e >> 5, k4 = (e & 31)*4;
        *reinterpret_cast<float4*>(&Xs[t*STR + k4]) =
            *reinterpret_cast<const float4*>(&Xsrc[(t0+t)*D + k4]);
    }
    if (!isW){
        const float* Al = g_A + layer*N*D;
        const float* Gl = g_G + layer*N*D;
        int s0 = b*SC;
        for (int e = tid; e < SC*32; e += 256){
            int r = e >> 5, k4 = (e & 31)*4;
            *reinterpret_cast<float4*>(&As[r*STR + k4]) =
                *reinterpret_cast<const float4*>(&Al[(s0+r)*D + k4]);
        }
        for (int e = tid; e < SC*32; e += 256){
            int r = e >> 5, k4 = (e & 31)*4;
            *reinterpret_cast<float4*>(&Gs[r*STR + k4]) =
                *reinterpret_cast<const float4*>(&Gl[(s0+r)*D + k4]);
        }
        for (int e = tid; e < TT*4; e += 256){
            int t = e >> 2, s4 = (e & 3)*4;
            *reinterpret_cast<float4*>(&Cs[t*CSTR + s4]) =
                *reinterpret_cast<const float4*>(&g_Chat[(t0+t)*N + s0 + s4]);
        }
    } else {
        const float* Wl = Wmem + layer*D*D;
        int w0 = b*WC;
        for (int e = tid; e < WC*32; e += 256){
            int r = e >> 5, k4 = (e & 31)*4;
            *reinterpret_cast<float4*>(&Gs[r*STR + k4]) =
                *reinterpret_cast<const float4*>(&Wl[(w0+r)*D + k4]);
        }
    }
    __syncthreads();

    // ---- phase 1 (real): S = (X @ A^T) ⊙ Chat -> Ps ----
    if (!isW){
        int sx16 = tid & 15;
        int tg   = tid >> 4;
        float c0 = 0.f, c1 = 0.f;
        const float* ar  = As + sx16*STR;
        const float* x0r = Xs + (tg*2+0)*STR;
        const float* x1r = Xs + (tg*2+1)*STR;
        #pragma unroll 8
        for (int k = 0; k < D; k += 4){
            float4 av = *reinterpret_cast<const float4*>(&ar[k]);
            float4 x0 = *reinterpret_cast<const float4*>(&x0r[k]);
            float4 x1 = *reinterpret_cast<const float4*>(&x1r[k]);
            c0 += x0.x*av.x + x0.y*av.y + x0.z*av.z + x0.w*av.w;
            c1 += x1.x*av.x + x1.y*av.y + x1.z*av.z + x1.w*av.w;
        }
        Ps[(tg*2+0)*PSTR + sx16] = c0 * Cs[(tg*2+0)*CSTR + sx16];
        Ps[(tg*2+1)*PSTR + sx16] = c1 * Cs[(tg*2+1)*CSTR + sx16];
    }
    __syncthreads();

    // ---- phase 2: Y_slice = P @ G ----
    int tx = tid & 31, ty = tid >> 5;
    const float* Psrc = isW ? (Xs + b*WC) : Ps;
    int pst = isW ? STR : PSTR;
    int sc  = isW ? WC : SC;

    float y[4][4];
    #pragma unroll
    for (int i = 0; i < 4; i++)
        #pragma unroll
        for (int jj = 0; jj < 4; jj++) y[i][jj] = 0.f;

    #pragma unroll 4
    for (int s = 0; s < sc; s += 4){
        float4 g0 = *reinterpret_cast<const float4*>(&Gs[(s+0)*STR + tx*4]);
        float4 g1 = *reinterpret_cast<const float4*>(&Gs[(s+1)*STR + tx*4]);
        float4 g2 = *reinterpret_cast<const float4*>(&Gs[(s+2)*STR + tx*4]);
        float4 g3 = *reinterpret_cast<const float4*>(&Gs[(s+3)*STR + tx*4]);
        #pragma unroll
        for (int i = 0; i < 4; i++){
            float4 p = *reinterpret_cast<const float4*>(&Psrc[(ty*4+i)*pst + s]);
            y[i][0] += p.x*g0.x + p.y*g1.x + p.z*g2.x + p.w*g3.x;
            y[i][1] += p.x*g0.y + p.y*g1.y + p.z*g2.y + p.w*g3.y;
            y[i][2] += p.x*g0.z + p.y*g1.z + p.z*g2.z + p.w*g3.z;
            y[i][3] += p.x*g0.w + p.y*g1.w + p.z*g2.w + p.w*g3.w;
        }
    }
    int slice = isW ? (32 + b) : b;
    #pragma unroll
    for (int i = 0; i < 4; i++){
        float4 v; v.x=y[i][0]; v.y=y[i][1]; v.z=y[i][2]; v.w=y[i][3];
        *reinterpret_cast<float4*>(&g_Yp[((slice*N) + t0 + ty*4 + i)*D + tx*4]) = v;
    }
}

// ---------------- reduce: slice-parallel, one block per token ----------------
__global__ __launch_bounds__(128) void reduce_kernel(float* __restrict__ out, int last){
    int t = blockIdx.x;
    int tid = threadIdx.x;
    int tx = tid & 31, sg = tid >> 5;
    const float4* Yp = reinterpret_cast<const float4*>(g_Yp);
    int idx = t*32 + tx;

    float4 acc = Yp[(32 + sg)*(N*32) + idx];

    int nr = (t >> 4) + 1;
    #pragma unroll 4
    for (int c = sg; c < nr; c += 4){
        float4 p = Yp[c*(N*32) + idx];
        acc.x += p.x; acc.y += p.y; acc.z += p.z; acc.w += p.w;
    }

    __shared__ float4 sred[128];
    sred[tid] = acc;
    __syncthreads();
    if (sg == 0){
        float4 a = sred[tx], b = sred[32+tx], c2 = sred[64+tx], d = sred[96+tx];
        float ax = a.x+b.x+c2.x+d.x;
        float ay = a.y+b.y+c2.y+d.y;
        float az = a.z+b.z+c2.z+d.z;
        float aw = a.w+b.w+c2.w+d.w;
        float4 r;
        if (last){ r.x = ax; r.y = ay; r.z = az; r.w = aw; }
        else     { r.x = siluf(ax); r.y = siluf(ay); r.z = siluf(az); r.w = siluf(aw); }
        float4* dst = last ? reinterpret_cast<float4*>(out) : reinterpret_cast<float4*>(g_X);
        dst[idx] = r;
    }
}

// ---------------- launch ----------------
extern "C" void kernel_launch(void* const* d_in, const int* in_sizes, int n_in,
                              void* d_out, int out_size){
    const float* seq    = (const float*)d_in[0];
    const float* Wmem   = (const float*)d_in[1];
    const float* Wq     = (const float*)d_in[2];
    const float* Wkv    = (const float*)d_in[3];
    const float* Wmom   = (const float*)d_in[4];
    const float* Wstep  = (const float*)d_in[5];
    const float* Wdecay = (const float*)d_in[6];
    float* out = (float*)d_out;

    size_t smem = (size_t)(TT*STR + SC*STR + WC*STR + TT*CSTR + TT*PSTR)*sizeof(float); // 47360
    cudaFuncSetAttribute(layer_kernel, cudaFuncAttributeMaxDynamicSharedMemorySize, (int)smem);

    tr_kernel<<<DEPTH, 128>>>(Wmem);
    token_kernel<<<N/2, 256>>>(seq, Wmem, Wq, Wkv, Wmom, Wstep, Wdecay);
    chat_kernel<<<4, 128>>>();

    layer_kernel<<<NBLK, 256, smem>>>(Wmem, 0, 1);
    reduce_kernel<<<N, 128>>>(out, 0);
    layer_kernel<<<NBLK, 256, smem>>>(Wmem, 1, 0);
    reduce_kernel<<<N, 128>>>(out, 0);
    layer_kernel<<<NBLK, 256, smem>>>(Wmem, 2, 0);
    reduce_kernel<<<N, 128>>>(out, 0);
    layer_kernel<<<NBLK, 256, smem>>>(Wmem, 3, 0);
    reduce_kernel<<<N, 128>>>(out, 1);
}

// round 17
// speedup vs baseline: 1.3003x; 1.0585x over previous
#include <cuda_runtime.h>
#include <math.h>

#define N 512
#define D 128
#define DEPTH 4
#define TT 32
#define SC 16            // real s-chunk size
#define WC 32            // W-chunk size
#define NREAL 272        // sum over a=0..15 of (2a+2)
#define NBLK 336         // 272 real + 64 W blocks
#define NSLICE 36        // 32 real + 4 W slices
#define STR 132
#define PSTR 20
#define CSTR 20

// ---------------- scratch ----------------
__device__ float g_q[N*D];
__device__ float g_X[N*D];
__device__ float g_lr[N], g_am[N], g_dk[N];
__device__ float g_A[DEPTH*N*D];
__device__ float g_G[DEPTH*N*D];
__device__ float g_WT[DEPTH*D*D];
__device__ float g_Chat[N*N];
__device__ float g_Yp[NSLICE*N*D];

__device__ __forceinline__ float siluf(float z){
    float s = 1.f/(1.f+__expf(-z));
    return z*s;
}
__device__ __forceinline__ float dsiluf(float z){
    float s = 1.f/(1.f+__expf(-z));
    return s*(1.f + z*(1.f-s));
}

// ---------------- no-op launch-slot shifters (ncu -s 5 lands on token_kernel) ----------------
__global__ void nop_kernel(){}

// ---------------- transpose W_mem ----------------
__global__ void tr_kernel(const float* __restrict__ Wmem){
    int l = blockIdx.x;
    for (int e = threadIdx.x; e < D*D; e += blockDim.x){
        int j = e >> 7, i = e & 127;
        g_WT[l*D*D + e] = Wmem[l*D*D + i*D + j];
    }
}

// ---------------- 32 column-strided weight loads into registers ----------------
__device__ __forceinline__ void ldw32(const float* __restrict__ p, float w[32]){
    #pragma unroll
    for (int u = 0; u < 32; u++) w[u] = p[u*D];
}

// ---------------- 4-token x 32-i FMA with preloaded weights ----------------
__device__ __forceinline__ void fmaw(const float sxa[4][D], const float w[32],
                                     int base, float z[4]){
    #pragma unroll
    for (int m = 0; m < 4; m++){
        const float* xr = &sxa[m][base];
        float a0 = 0.f, a1 = 0.f;
        #pragma unroll
        for (int q = 0; q < 32; q += 8){
            float4 xa = *reinterpret_cast<const float4*>(&xr[q]);
            float4 xb = *reinterpret_cast<const float4*>(&xr[q+4]);
            a0 += xa.x*w[q]   + xa.y*w[q+1] + xa.z*w[q+2] + xa.w*w[q+3];
            a1 += xb.x*w[q+4] + xb.y*w[q+5] + xb.z*w[q+6] + xb.w*w[q+7];
        }
        z[m] = a0 + a1;
    }
}

// ---------------- per-token MLP fwd+bwd: 4 tokens/block, 512 thr (i split in 4) ----------------
__global__ __launch_bounds__(512) void token_kernel(const float* __restrict__ seq,
                             const float* __restrict__ Wmem,
                             const float* __restrict__ Wq,
                             const float* __restrict__ Wkv,
                             const float* __restrict__ Wmom,
                             const float* __restrict__ Wstep,
                             const float* __restrict__ Wdecay){
    int t0 = blockIdx.x*4;
    int tid = threadIdx.x;
    int j  = tid & 127;
    int qt = tid >> 7;                    // quarter 0..3
    const int base = qt*32;
    const int coff = base*D + j;          // weight stream offset for this thread

    __shared__ float sx[4][D];
    __shared__ float sA[4][D];
    __shared__ float sB[4][D];
    __shared__ float sv[4][D];
    __shared__ float szp[3][4][4][D];     // [stream][quarter][token][j]
    __shared__ float red[12][4];

    for (int e = tid; e < 4*D; e += 512){
        int m = e >> 7, jj = e & 127;
        sx[m][jj] = seq[(t0+m)*D + jj];
    }
    __syncthreads();

    if (qt == 0){
        float ws = Wstep[j], wm = Wmom[j], wd = Wdecay[j];
        #pragma unroll
        for (int m = 0; m < 4; m++){
            float xv = sx[m][j];
            float p0 = xv*ws, p1 = xv*wm, p2 = xv*wd;
            #pragma unroll
            for (int o = 16; o > 0; o >>= 1){
                p0 += __shfl_xor_sync(0xffffffffu, p0, o);
                p1 += __shfl_xor_sync(0xffffffffu, p1, o);
                p2 += __shfl_xor_sync(0xffffffffu, p2, o);
            }
            if ((j & 31) == 0){ red[m*3+0][j>>5]=p0; red[m*3+1][j>>5]=p1; red[m*3+2][j>>5]=p2; }
        }
    }

    // prefetch stage-0 weights while q/k/v runs
    float wA[32], wB[32];
    ldw32(Wmem + coff, wA);

    // q,k,v partials over this thread's 32-i quarter
    {
        float qa[4]={0,0,0,0}, ka[4]={0,0,0,0}, va[4]={0,0,0,0};
        const float* Wqh  = Wq  + base*D + j;
        const float* Wkh  = Wkv + base*2*D + j;
        const float* Wvh  = Wkv + base*2*D + D + j;
        for (int i = 0; i < 32; i += 8){
            float wq[8], wk[8], wv[8];
            #pragma unroll
            for (int u = 0; u < 8; u++){
                wq[u] = Wqh[(i+u)*D];
                wk[u] = Wkh[(i+u)*2*D];
                wv[u] = Wvh[(i+u)*2*D];
            }
            #pragma unroll
            for (int m = 0; m < 4; m++){
                const float* xr = &sx[m][base+i];
                float4 xa = *reinterpret_cast<const float4*>(&xr[0]);
                float4 xb = *reinterpret_cast<const float4*>(&xr[4]);
                qa[m] += xa.x*wq[0]+xa.y*wq[1]+xa.z*wq[2]+xa.w*wq[3]
                       + xb.x*wq[4]+xb.y*wq[5]+xb.z*wq[6]+xb.w*wq[7];
                ka[m] += xa.x*wk[0]+xa.y*wk[1]+xa.z*wk[2]+xa.w*wk[3]
                       + xb.x*wk[4]+xb.y*wk[5]+xb.z*wk[6]+xb.w*wk[7];
                va[m] += xa.x*wv[0]+xa.y*wv[1]+xa.z*wv[2]+xa.w*wv[3]
                       + xb.x*wv[4]+xb.y*wv[5]+xb.z*wv[6]+xb.w*wv[7];
            }
        }
        #pragma unroll
        for (int m = 0; m < 4; m++){
            szp[0][qt][m][j] = qa[m];
            szp[1][qt][m][j] = ka[m];
            szp[2][qt][m][j] = va[m];
        }
    }
    __syncthreads();
    if (qt == 0){
        if (j < 4){
            g_lr[t0+j] = red[j*3+0][0]+red[j*3+0][1]+red[j*3+0][2]+red[j*3+0][3];
            g_am[t0+j] = red[j*3+1][0]+red[j*3+1][1]+red[j*3+1][2]+red[j*3+1][3];
            float dz = red[j*3+2][0]+red[j*3+2][1]+red[j*3+2][2]+red[j*3+2][3];
            g_dk[t0+j] = 1.f - 1.f/(1.f+__expf(-dz));
        }
        #pragma unroll
        for (int m = 0; m < 4; m++){
            g_q[(t0+m)*D + j] = szp[0][0][m][j]+szp[0][1][m][j]+szp[0][2][m][j]+szp[0][3][m][j];
            float kk = szp[1][0][m][j]+szp[1][1][m][j]+szp[1][2][m][j]+szp[1][3][m][j];
            sA[m][j] = kk; g_A[0*N*D + (t0+m)*D + j] = kk;
            sv[m][j] = szp[2][0][m][j]+szp[2][1][m][j]+szp[2][2][m][j]+szp[2][3][m][j];
        }
    }
    __syncthreads();

    float z1[4], z2[4], z3[4], zp[4], z[4];

    #define COMBINE(m) (szp[0][0][m][j]+szp[0][1][m][j]+szp[0][2][m][j]+szp[0][3][m][j])

    // stage 0: z1 = k @ W0  (wA; prefetch W1 -> wB)
    ldw32(Wmem + 1*D*D + coff, wB);
    fmaw(sA, wA, base, zp);
    #pragma unroll
    for (int m = 0; m < 4; m++) szp[0][qt][m][j] = zp[m];
    __syncthreads();
    #pragma unroll
    for (int m = 0; m < 4; m++){
        z[m] = COMBINE(m); z1[m] = z[m];
        if (qt == 0){ float x1 = siluf(z[m]); sB[m][j] = x1; g_A[1*N*D + (t0+m)*D + j] = x1; }
    }
    __syncthreads();

    // stage 1: z2 = x1 @ W1  (wB; prefetch W2 -> wA)
    ldw32(Wmem + 2*D*D + coff, wA);
    fmaw(sB, wB, base, zp);
    #pragma unroll
    for (int m = 0; m < 4; m++) szp[0][qt][m][j] = zp[m];
    __syncthreads();
    #pragma unroll
    for (int m = 0; m < 4; m++){
        z[m] = COMBINE(m); z2[m] = z[m];
        if (qt == 0){ float x2 = siluf(z[m]); sA[m][j] = x2; g_A[2*N*D + (t0+m)*D + j] = x2; }
    }
    __syncthreads();

    // stage 2: z3 = x2 @ W2  (wA; prefetch W3 -> wB)
    ldw32(Wmem + 3*D*D + coff, wB);
    fmaw(sA, wA, base, zp);
    #pragma unroll
    for (int m = 0; m < 4; m++) szp[0][qt][m][j] = zp[m];
    __syncthreads();
    #pragma unroll
    for (int m = 0; m < 4; m++){
        z[m] = COMBINE(m); z3[m] = z[m];
        if (qt == 0){ float x3 = siluf(z[m]); sB[m][j] = x3; g_A[3*N*D + (t0+m)*D + j] = x3; }
    }
    __syncthreads();

    // stage 3: z4 = x3 @ W3 ; g3  (wB; prefetch WT3 -> wA)
    ldw32(g_WT + 3*D*D + coff, wA);
    fmaw(sB, wB, base, zp);
    #pragma unroll
    for (int m = 0; m < 4; m++) szp[0][qt][m][j] = zp[m];
    __syncthreads();
    #pragma unroll
    for (int m = 0; m < 4; m++){
        z[m] = COMBINE(m);
        if (qt == 0){
            float gg = (z[m] - sv[m][j]) * (2.f/(float)D);
            sA[m][j] = gg; g_G[3*N*D + (t0+m)*D + j] = gg;
        }
    }
    __syncthreads();

    // stage 4: dx = g3 @ W3^T ; g2  (wA; prefetch WT2 -> wB)
    ldw32(g_WT + 2*D*D + coff, wB);
    fmaw(sA, wA, base, zp);
    #pragma unroll
    for (int m = 0; m < 4; m++) szp[0][qt][m][j] = zp[m];
    __syncthreads();
    #pragma unroll
    for (int m = 0; m < 4; m++){
        z[m] = COMBINE(m);
        if (qt == 0){
            float gg = z[m]*dsiluf(z3[m]);
            sB[m][j] = gg; g_G[2*N*D + (t0+m)*D + j] = gg;
        }
    }
    __syncthreads();

    // stage 5: dx = g2 @ W2^T ; g1  (wB; prefetch WT1 -> wA)
    ldw32(g_WT + 1*D*D + coff, wA);
    fmaw(sB, wB, base, zp);
    #pragma unroll
    for (int m = 0; m < 4; m++) szp[0][qt][m][j] = zp[m];
    __syncthreads();
    #pragma unroll
    for (int m = 0; m < 4; m++){
        z[m] = COMBINE(m);
        if (qt == 0){
            float gg = z[m]*dsiluf(z2[m]);
            sA[m][j] = gg; g_G[1*N*D + (t0+m)*D + j] = gg;
        }
    }
    __syncthreads();

    // stage 6: dx = g1 @ W1^T ; g0  (wA)
    fmaw(sA, wA, base, zp);
    #pragma unroll
    for (int m = 0; m < 4; m++) szp[0][qt][m][j] = zp[m];
    __syncthreads();
    if (qt == 0){
        #pragma unroll
        for (int m = 0; m < 4; m++){
            float zz = COMBINE(m);
            g_G[0*N*D + (t0+m)*D + j] = zz*dsiluf(z1[m]);
        }
    }
    #undef COMBINE
}

// ---------------- scan-coefficient matrix (parallel over s) ----------------
__global__ void chat_kernel(){
    __shared__ float sam[N], sdk[N];
    int s = blockIdx.x*128 + threadIdx.x;
    for (int i = threadIdx.x; i < N; i += 128){ sam[i] = g_am[i]; sdk[i] = g_dk[i]; }
    __syncthreads();
    float m = 0.f, c = 0.f;
    float nl = -g_lr[s];
    for (int t = 0; t < N; t++){
        float out;
        if (t < s) out = 0.f;
        else if (t == s){ m = 1.f; c = 1.f; out = nl; }
        else {
            m *= sam[t];
            c = sdk[t]*c + m;
            out = nl*c;
        }
        g_Chat[t*N + s] = out;
    }
}

// ---------------- fused attention layer (measured-best config) ----------------
__global__ __launch_bounds__(256) void layer_kernel(const float* __restrict__ Wmem,
                                                    int layer, int first){
    extern __shared__ float sm[];
    float* Xs = sm;                 // [TT][STR]
    float* As = Xs + TT*STR;        // [SC][STR]
    float* Gs = As + SC*STR;        // [WC][STR]
    float* Cs = Gs + WC*STR;        // [TT][CSTR]
    float* Ps = Cs + TT*CSTR;       // [TT][PSTR]

    int id = blockIdx.x;
    int a, b; bool isW;
    if (id < NREAL){
        int r = id; a = 0;
        while (r >= 2*a + 2){ r -= 2*a + 2; a++; }
        b = r; isW = false;
    } else {
        int q = id - NREAL; a = q >> 2; b = q & 3; isW = true;
    }
    int t0 = a*TT;
    int tid = threadIdx.x;

    const float* Xsrc = first ? g_q : g_X;
    for (int e = tid; e < TT*32; e += 256){
        int t = e >> 5, k4 = (e & 31)*4;
        *reinterpret_cast<float4*>(&Xs[t*STR + k4]) =
            *reinterpret_cast<const float4*>(&Xsrc[(t0+t)*D + k4]);
    }
    if (!isW){
        const float* Al = g_A + layer*N*D;
        const float* Gl = g_G + layer*N*D;
        int s0 = b*SC;
        for (int e = tid; e < SC*32; e += 256){
            int r = e >> 5, k4 = (e & 31)*4;
            *reinterpret_cast<float4*>(&As[r*STR + k4]) =
                *reinterpret_cast<const float4*>(&Al[(s0+r)*D + k4]);
        }
        for (int e = tid; e < SC*32; e += 256){
            int r = e >> 5, k4 = (e & 31)*4;
            *reinterpret_cast<float4*>(&Gs[r*STR + k4]) =
                *reinterpret_cast<const float4*>(&Gl[(s0+r)*D + k4]);
        }
        for (int e = tid; e < TT*4; e += 256){
            int t = e >> 2, s4 = (e & 3)*4;
            *reinterpret_cast<float4*>(&Cs[t*CSTR + s4]) =
                *reinterpret_cast<const float4*>(&g_Chat[(t0+t)*N + s0 + s4]);
        }
    } else {
        const float* Wl = Wmem + layer*D*D;
        int w0 = b*WC;
        for (int e = tid; e < WC*32; e += 256){
            int r = e >> 5, k4 = (e & 31)*4;
            *reinterpret_cast<float4*>(&Gs[r*STR + k4]) =
                *reinterpret_cast<const float4*>(&Wl[(w0+r)*D + k4]);
        }
    }
    __syncthreads();

    // ---- phase 1 (real): S = (X @ A^T) ⊙ Chat -> Ps ----
    if (!isW){
        int sx16 = tid & 15;
        int tg   = tid >> 4;
        float c0 = 0.f, c1 = 0.f;
        const float* ar  = As + sx16*STR;
        const float* x0r = Xs + (tg*2+0)*STR;
        const float* x1r = Xs + (tg*2+1)*STR;
        #pragma unroll 8
        for (int k = 0; k < D; k += 4){
            float4 av = *reinterpret_cast<const float4*>(&ar[k]);
            float4 x0 = *reinterpret_cast<const float4*>(&x0r[k]);
            float4 x1 = *reinterpret_cast<const float4*>(&x1r[k]);
            c0 += x0.x*av.x + x0.y*av.y + x0.z*av.z + x0.w*av.w;
            c1 += x1.x*av.x + x1.y*av.y + x1.z*av.z + x1.w*av.w;
        }
        Ps[(tg*2+0)*PSTR + sx16] = c0 * Cs[(tg*2+0)*CSTR + sx16];
        Ps[(tg*2+1)*PSTR + sx16] = c1 * Cs[(tg*2+1)*CSTR + sx16];
    }
    __syncthreads();

    // ---- phase 2: Y_slice = P @ G ----
    int tx = tid & 31, ty = tid >> 5;
    const float* Psrc = isW ? (Xs + b*WC) : Ps;
    int pst = isW ? STR : PSTR;
    int sc  = isW ? WC : SC;

    float y[4][4];
    #pragma unroll
    for (int i = 0; i < 4; i++)
        #pragma unroll
        for (int jj = 0; jj < 4; jj++) y[i][jj] = 0.f;

    #pragma unroll 4
    for (int s = 0; s < sc; s += 4){
        float4 g0 = *reinterpret_cast<const float4*>(&Gs[(s+0)*STR + tx*4]);
        float4 g1 = *reinterpret_cast<const float4*>(&Gs[(s+1)*STR + tx*4]);
        float4 g2 = *reinterpret_cast<const float4*>(&Gs[(s+2)*STR + tx*4]);
        float4 g3 = *reinterpret_cast<const float4*>(&Gs[(s+3)*STR + tx*4]);
        #pragma unroll
        for (int i = 0; i < 4; i++){
            float4 p = *reinterpret_cast<const float4*>(&Psrc[(ty*4+i)*pst + s]);
            y[i][0] += p.x*g0.x + p.y*g1.x + p.z*g2.x + p.w*g3.x;
            y[i][1] += p.x*g0.y + p.y*g1.y + p.z*g2.y + p.w*g3.y;
            y[i][2] += p.x*g0.z + p.y*g1.z + p.z*g2.z + p.w*g3.z;
            y[i][3] += p.x*g0.w + p.y*g1.w + p.z*g2.w + p.w*g3.w;
        }
    }
    int slice = isW ? (32 + b) : b;
    #pragma unroll
    for (int i = 0; i < 4; i++){
        float4 v; v.x=y[i][0]; v.y=y[i][1]; v.z=y[i][2]; v.w=y[i][3];
        *reinterpret_cast<float4*>(&g_Yp[((slice*N) + t0 + ty*4 + i)*D + tx*4]) = v;
    }
}

// ---------------- reduce: slice-parallel, one block per token ----------------
__global__ __launch_bounds__(128) void reduce_kernel(float* __restrict__ out, int last){
    int t = blockIdx.x;
    int tid = threadIdx.x;
    int tx = tid & 31, sg = tid >> 5;
    const float4* Yp = reinterpret_cast<const float4*>(g_Yp);
    int idx = t*32 + tx;

    float4 acc = Yp[(32 + sg)*(N*32) + idx];

    int nr = (t >> 4) + 1;
    #pragma unroll 4
    for (int c = sg; c < nr; c += 4){
        float4 p = Yp[c*(N*32) + idx];
        acc.x += p.x; acc.y += p.y; acc.z += p.z; acc.w += p.w;
    }

    __shared__ float4 sred[128];
    sred[tid] = acc;
    __syncthreads();
    if (sg == 0){
        float4 a = sred[tx], b = sred[32+tx], c2 = sred[64+tx], d = sred[96+tx];
        float ax = a.x+b.x+c2.x+d.x;
        float ay = a.y+b.y+c2.y+d.y;
        float az = a.z+b.z+c2.z+d.z;
        float aw = a.w+b.w+c2.w+d.w;
        float4 r;
        if (last){ r.x = ax; r.y = ay; r.z = az; r.w = aw; }
        else     { r.x = siluf(ax); r.y = siluf(ay); r.z = siluf(az); r.w = siluf(aw); }
        float4* dst = last ? reinterpret_cast<float4*>(out) : reinterpret_cast<float4*>(g_X);
        dst[idx] = r;
    }
}

// ---------------- launch ----------------
extern "C" void kernel_launch(void* const* d_in, const int* in_sizes, int n_in,
                              void* d_out, int out_size){
    const float* seq    = (const float*)d_in[0];
    const float* Wmem   = (const float*)d_in[1];
    const float* Wq     = (const float*)d_in[2];
    const float* Wkv    = (const float*)d_in[3];
    const float* Wmom   = (const float*)d_in[4];
    const float* Wstep  = (const float*)d_in[5];
    const float* Wdecay = (const float*)d_in[6];
    float* out = (float*)d_out;

    size_t smem = (size_t)(TT*STR + SC*STR + WC*STR + TT*CSTR + TT*PSTR)*sizeof(float); // 47360
    cudaFuncSetAttribute(layer_kernel, cudaFuncAttributeMaxDynamicSharedMemorySize, (int)smem);

    // 2 nops: harness pre-launches(2) + nops(2) + tr(1) => token_kernel is launch #6 (ncu -s 5)
    nop_kernel<<<1, 32>>>();
    nop_kernel<<<1, 32>>>();

    tr_kernel<<<DEPTH, 128>>>(Wmem);
    token_kernel<<<N/4, 512>>>(seq, Wmem, Wq, Wkv, Wmom, Wstep, Wdecay);
    chat_kernel<<<4, 128>>>();

    layer_kernel<<<NBLK, 256, smem>>>(Wmem, 0, 1);
    reduce_kernel<<<N, 128>>>(out, 0);
    layer_kernel<<<NBLK, 256, smem>>>(Wmem, 1, 0);
    reduce_kernel<<<N, 128>>>(out, 0);
    layer_kernel<<<NBLK, 256, smem>>>(Wmem, 2, 0);
    reduce_kernel<<<N, 128>>>(out, 0);
    layer_kernel<<<NBLK, 256, smem>>>(Wmem, 3, 0);
    reduce_kernel<<<N, 128>>>(out, 1);
}